// round 6
// baseline (speedup 1.0000x reference)
#include <cuda_runtime.h>

#define BS 16
#define SS 2048
#define HH 1024
#define DD 32
#define CC 8
#define LL 3
#define NSPAN (BS * DD)     // 512
#define NBLK  (NSPAN * 2)   // 1024 — two half-span blocks per span

// partial logits per block (block = 2*span + half), rewritten every launch
__device__ float g_part[NBLK * LL];
// completion counter for last-block-done combine (reset by the tail block)
__device__ unsigned int g_count = 0;

__device__ __forceinline__ int load_int(const void* p, int i, bool is64) {
    if (is64) return (int)((const long long*)p)[i];
    return ((const int*)p)[i];
}

// gpu-scope release add: orders this block's prior global stores at L2 without
// the per-block CCTL.IVALL that __threadfence() costs.
__device__ __forceinline__ unsigned int atom_add_release_gpu(unsigned int* p, unsigned int v) {
    unsigned int prev;
    asm volatile("atom.add.release.gpu.global.u32 %0, [%1], %2;"
                 : "=r"(prev) : "l"(p), "r"(v) : "memory");
    return prev;
}

__global__ void __launch_bounds__(256)
fused_kernel(const float* __restrict__ enc,
             const float* __restrict__ W,
             const float* __restrict__ bias,
             const void* __restrict__ headp,
             const void* __restrict__ tailp,
             const void* __restrict__ dtp,
             const void* __restrict__ labp,
             float* __restrict__ d_out, int out_size)
{
    const int blk  = blockIdx.x;
    const int span = blk >> 1;
    const int half = blk & 1;
    const int t    = threadIdx.x;      // 0..255

    // ---- parallel int32-vs-int64 layout detection (odd high-words all zero) ----
    __shared__ int s_flags;
    if (t == 0) s_flags = 0;
    __syncthreads();
    {
        const int w = 2 * t + 1;       // odd words 1..511
        int f = 0;
        if (((const int*)headp)[w]) f |= 1;
        if (((const int*)tailp)[w]) f |= 2;
        if (((const int*)dtp)[w])   f |= 4;
        if (((const int*)labp)[w])  f |= 8;
        if (f) atomicOr(&s_flags, f);
    }
    __syncthreads();
    const int flags = s_flags;
    const bool h64 = !(flags & 1);
    const bool t64 = !(flags & 2);
    const bool c64 = !(flags & 4);
    const bool l64 = !(flags & 8);

    const int s0 = load_int(headp, span, h64) + 1;     // mask starts at head+1
    const int n  = load_int(tailp, span, t64) - s0;    // typically 63
    const int c  = load_int(dtp,   span, c64);
    const int b  = span / DD;

    // this half's row range
    const int hn = (n + 1) >> 1;
    const int r0 = half * hn;
    const int r1 = (r0 + hn < n) ? (r0 + hn) : n;
    const int nr = r1 - r0;

    const float4* base =
        (const float4*)(enc + ((size_t)b * SS + (size_t)(s0 + r0)) * HH) + t;
    const int rowstep = HH / 4;

    float4 acc = make_float4(0.f, 0.f, 0.f, 0.f);
    int i = 0;
    // 8 independent LDG.128 in flight per thread
    for (; i + 8 <= nr; i += 8) {
        float4 v0 = __ldcs(base + (size_t)(i + 0) * rowstep);
        float4 v1 = __ldcs(base + (size_t)(i + 1) * rowstep);
        float4 v2 = __ldcs(base + (size_t)(i + 2) * rowstep);
        float4 v3 = __ldcs(base + (size_t)(i + 3) * rowstep);
        float4 v4 = __ldcs(base + (size_t)(i + 4) * rowstep);
        float4 v5 = __ldcs(base + (size_t)(i + 5) * rowstep);
        float4 v6 = __ldcs(base + (size_t)(i + 6) * rowstep);
        float4 v7 = __ldcs(base + (size_t)(i + 7) * rowstep);
        acc.x += ((v0.x + v1.x) + (v2.x + v3.x)) + ((v4.x + v5.x) + (v6.x + v7.x));
        acc.y += ((v0.y + v1.y) + (v2.y + v3.y)) + ((v4.y + v5.y) + (v6.y + v7.y));
        acc.z += ((v0.z + v1.z) + (v2.z + v3.z)) + ((v4.z + v5.z) + (v6.z + v7.z));
        acc.w += ((v0.w + v1.w) + (v2.w + v3.w)) + ((v4.w + v5.w) + (v6.w + v7.w));
    }
    for (; i + 4 <= nr; i += 4) {
        float4 v0 = __ldcs(base + (size_t)(i + 0) * rowstep);
        float4 v1 = __ldcs(base + (size_t)(i + 1) * rowstep);
        float4 v2 = __ldcs(base + (size_t)(i + 2) * rowstep);
        float4 v3 = __ldcs(base + (size_t)(i + 3) * rowstep);
        acc.x += (v0.x + v1.x) + (v2.x + v3.x);
        acc.y += (v0.y + v1.y) + (v2.y + v3.y);
        acc.z += (v0.z + v1.z) + (v2.z + v3.z);
        acc.w += (v0.w + v1.w) + (v2.w + v3.w);
    }
    for (; i < nr; i++) {
        float4 v = __ldcs(base + (size_t)i * rowstep);
        acc.x += v.x; acc.y += v.y; acc.z += v.z; acc.w += v.w;
    }

    // partial GEMV against W[c] (un-normalized, no bias — linear)
    const int h0 = t * 4;
    const float* Wc = W + (size_t)c * HH * LL;

    float l0 = acc.x * __ldg(&Wc[(h0 + 0) * LL + 0]) + acc.y * __ldg(&Wc[(h0 + 1) * LL + 0])
             + acc.z * __ldg(&Wc[(h0 + 2) * LL + 0]) + acc.w * __ldg(&Wc[(h0 + 3) * LL + 0]);
    float l1 = acc.x * __ldg(&Wc[(h0 + 0) * LL + 1]) + acc.y * __ldg(&Wc[(h0 + 1) * LL + 1])
             + acc.z * __ldg(&Wc[(h0 + 2) * LL + 1]) + acc.w * __ldg(&Wc[(h0 + 3) * LL + 1]);
    float l2 = acc.x * __ldg(&Wc[(h0 + 0) * LL + 2]) + acc.y * __ldg(&Wc[(h0 + 1) * LL + 2])
             + acc.z * __ldg(&Wc[(h0 + 2) * LL + 2]) + acc.w * __ldg(&Wc[(h0 + 3) * LL + 2]);

    #pragma unroll
    for (int o = 16; o > 0; o >>= 1) {
        l0 += __shfl_down_sync(0xffffffffu, l0, o);
        l1 += __shfl_down_sync(0xffffffffu, l1, o);
        l2 += __shfl_down_sync(0xffffffffu, l2, o);
    }

    __shared__ float sred[8][3];
    {
        const int w = t >> 5, lane = t & 31;
        if (lane == 0) { sred[w][0] = l0; sred[w][1] = l1; sred[w][2] = l2; }
    }
    __syncthreads();

    if (t < LL) {
        float s = 0.f;
        #pragma unroll
        for (int k = 0; k < 8; k++) s += sred[k][t];
        g_part[blk * LL + t] = s;
    }

    // ---- last-block-done election: release atomic, NO per-block gpu fence ----
    __shared__ int s_last;
    __syncthreads();                   // t<3 stores ordered before t0's release
    if (t == 0) {
        unsigned int prev = atom_add_release_gpu(&g_count, 1u);
        s_last = (prev == NBLK - 1) ? 1 : 0;
        if (s_last) {
            g_count = 0;               // reset for next graph replay
            __threadfence();           // acquire side — paid ONCE, by one block
        }
    }
    __syncthreads();
    if (!s_last) return;

    // ---- Phase 2: combine + loss (one block, 256 threads, 2 spans each) ----
    float nll = 0.f, vf = 0.f;
    #pragma unroll
    for (int k = 0; k < 2; k++) {
        const int sp = t + k * 256;    // span 0..511

        const int ss0 = load_int(headp, sp, h64) + 1;
        const int sn  = load_int(tailp, sp, t64) - ss0;
        const int sc  = load_int(dtp,   sp, c64);
        const int lab = load_int(labp,  sp, l64);

        const float inv = 1.0f / (float)sn;
        // L2-direct reads of other blocks' partials
        const float x0 = (__ldcg(&g_part[(2 * sp) * LL + 0]) + __ldcg(&g_part[(2 * sp + 1) * LL + 0])) * inv + __ldg(&bias[sc * LL + 0]);
        const float x1 = (__ldcg(&g_part[(2 * sp) * LL + 1]) + __ldcg(&g_part[(2 * sp + 1) * LL + 1])) * inv + __ldg(&bias[sc * LL + 1]);
        const float x2 = (__ldcg(&g_part[(2 * sp) * LL + 2]) + __ldcg(&g_part[(2 * sp + 1) * LL + 2])) * inv + __ldg(&bias[sc * LL + 2]);

        if (out_size >= NSPAN * LL) {
            d_out[sp * LL + 0] = x0;
            d_out[sp * LL + 1] = x1;
            d_out[sp * LL + 2] = x2;
        }

        const float m   = fmaxf(x0, fmaxf(x1, x2));
        const float lse = m + logf(expf(x0 - m) + expf(x1 - m) + expf(x2 - m));
        const bool valid = (lab >= 0);
        const float xl = valid ? ((lab == 0) ? x0 : ((lab == 1) ? x1 : x2)) : 0.f;
        nll += valid ? (lse - xl) : 0.f;
        vf  += valid ? 1.f : 0.f;
    }

    #pragma unroll
    for (int o = 16; o > 0; o >>= 1) {
        nll += __shfl_down_sync(0xffffffffu, nll, o);
        vf  += __shfl_down_sync(0xffffffffu, vf,  o);
    }
    __shared__ float s_n[8], s_v[8];
    const int w = t >> 5, lane = t & 31;
    if (lane == 0) { s_n[w] = nll; s_v[w] = vf; }
    __syncthreads();
    if (t == 0) {
        float a = 0.f, v = 0.f;
        #pragma unroll
        for (int k = 0; k < 8; k++) { a += s_n[k]; v += s_v[k]; }
        const float loss = a / v;
        if (out_size >= NSPAN * LL + 1)  d_out[NSPAN * LL] = loss;
        else if (out_size < NSPAN * LL)  d_out[0] = loss;
    }
}

extern "C" void kernel_launch(void* const* d_in, const int* in_sizes, int n_in,
                              void* d_out, int out_size)
{
    const float* enc  = (const float*)d_in[0];   // encoder_layer (BS,S,H) f32
    const float* W    = (const float*)d_in[1];   // (C,H,L) f32
    const float* bias = (const float*)d_in[2];   // (C,L)   f32
    const void*  head = d_in[3];                 // (BS,D) int32 or int64
    const void*  tail = d_in[4];
    const void*  dtid = d_in[5];
    const void*  labs = d_in[6];

    fused_kernel<<<NBLK, 256>>>(enc, W, bias, head, tail, dtid, labs,
                                (float*)d_out, out_size);
}